// round 10
// baseline (speedup 1.0000x reference)
#include <cuda_runtime.h>
#include <cuda_bf16.h>
#include <mma.h>
#include <stdint.h>
#include <math.h>

using namespace nvcuda;

#define SEQ 2048
#define DIM 4096
#define NH 32
#define NKV 8
#define HD 128
#define KVD (NKV*HD)   // 1024

typedef __nv_bfloat16 bf16;

// ================= scratch (no cudaMalloc allowed) =================
__device__ float g_scores[(size_t)NH * SEQ * SEQ];              // 512 MB
__device__ float g_stat_m[NH * 16 * SEQ];                       // per-(h,tile,row) max
__device__ float g_stat_s[NH * 16 * SEQ];                       // per-(h,tile,row) sumexp
__device__ float g_rowM[NH * SEQ];                              // global row max
__device__ float g_linv[NH * SEQ];                              // 1/rowsum
__device__ bf16 g_xh[SEQ * DIM],  g_xl[SEQ * DIM];
__device__ bf16 g_wqh[DIM * DIM], g_wql[DIM * DIM];
__device__ bf16 g_wkh[KVD * DIM], g_wkl[KVD * DIM];
__device__ bf16 g_wvh[KVD * DIM], g_wvl[KVD * DIM];
__device__ bf16 g_woh[DIM * DIM], g_wol[DIM * DIM];
__device__ bf16 g_qh[SEQ * DIM],  g_ql[SEQ * DIM];
__device__ bf16 g_kh[SEQ * KVD],  g_kl[SEQ * KVD];
__device__ bf16 g_vth[KVD * SEQ], g_vtl[KVD * SEQ];             // V transposed [d, t]
__device__ bf16 g_ah[SEQ * DIM],  g_al[SEQ * DIM];

#define SOFT_SCALE 0.08838834764831845f   // 1/sqrt(128)

// ================= cp.async helpers =================
__device__ __forceinline__ void cpa16(uint32_t dst, const void* src) {
    unsigned long long g = (unsigned long long)__cvta_generic_to_global(src);
    asm volatile("cp.async.cg.shared.global [%0], [%1], 16;" :: "r"(dst), "l"(g) : "memory");
}
#define CPA_COMMIT() asm volatile("cp.async.commit_group;" ::: "memory")
#define CPA_WAIT(n)  asm volatile("cp.async.wait_group %0;" :: "n"(n) : "memory")

__device__ __forceinline__ void split2(float v0, float v1, bf16* ph, bf16* pl) {
    bf16 h0 = __float2bfloat16(v0), h1 = __float2bfloat16(v1);
    bf16 l0 = __float2bfloat16(v0 - __bfloat162float(h0));
    bf16 l1 = __float2bfloat16(v1 - __bfloat162float(h1));
    *(__nv_bfloat162*)ph = __halves2bfloat162(h0, h1);
    *(__nv_bfloat162*)pl = __halves2bfloat162(l0, l1);
}

// ================= 3-pass bf16 HMMA GEMM =================
// C[M,N] = Ah*Bh^T + Ah*Bl^T + Al*Bh^T   (TN, row-major, 128x128 CTA tiles)
// MODE 0: generic fp32 C.
// MODE 1: scores (per-head, triangular grid), fp32 C + per-tile row stats.
// MODE 2: PV. A operand built on the fly: reads fp32 scores, applies
//         exp(s*scale - Mrow) + causal mask, hi/lo split into smem.
//         Epilogue multiplies by 1/L. bf16 hi/lo C.
// MODE 3: projection + RoPE + bf16 hi/lo C (Q and K projections).
// MODE 4: projection + transpose + bf16 hi/lo C (V projection).
#define TSTRIDE 40
#define TILE_E  (128 * TSTRIDE)          // 5120 elements per tile
#define CHUNK_E (4 * TILE_E)             // 20480 elements per buffer (40KB)
#define GSMEM   (2 * CHUNK_E * 2)        // 81920 bytes (>= 67584 staging)
#define SSTR    132                      // fp32 staging stride

template<int MODE>
__global__ void __launch_bounds__(256) gemm3_kernel(
    const bf16* __restrict__ Ah, const bf16* __restrict__ Al,
    const bf16* __restrict__ Bh, const bf16* __restrict__ Bl,
    float* __restrict__ Cf, bf16* __restrict__ Ch, bf16* __restrict__ Cl,
    const float* __restrict__ Linv, const float* __restrict__ Mrow,
    float* __restrict__ Sm, float* __restrict__ Ss,
    int K, int lda, int ldb, int ldc)
{
    int m0, n0;
    if (MODE == 1) {
        // triangular decode: blockIdx.x in [0, 136)
        const int L = blockIdx.x;
        int s0i = (int)((sqrtf(8.0f * (float)L + 1.0f) - 1.0f) * 0.5f);
        while ((s0i + 1) * (s0i + 2) / 2 <= L) s0i++;
        while (s0i * (s0i + 1) / 2 > L) s0i--;
        m0 = s0i * 128;
        n0 = (L - s0i * (s0i + 1) / 2) * 128;
    } else if (MODE == 2) {
        m0 = (int)(gridDim.y - 1 - blockIdx.y) * 128;   // heavy tiles first
        n0 = blockIdx.x * 128;
    } else {
        m0 = blockIdx.y * 128;
        n0 = blockIdx.x * 128;
    }
    const int h = blockIdx.z, kvh = h >> 2;
    const int tid = threadIdx.x;
    const int warp = tid >> 5;
    const int wm = warp >> 1;           // 0..3  (32-row slice)
    const int wn = warp & 1;            // 0..1  (64-col slice)

    size_t aoff = 0, boff, coff = 0;
    int kLen = K;
    if (MODE == 1)      { aoff = (size_t)m0 * lda + (size_t)h * HD;  boff = (size_t)n0 * ldb + (size_t)kvh * HD;
                          coff = (size_t)h * SEQ * SEQ; }
    else if (MODE == 2) { boff = (size_t)(kvh * HD) * ldb;           kLen = m0 + 128; }
    else                { aoff = (size_t)m0 * lda;                   boff = (size_t)n0 * ldb; }
    const bf16* pAh = Ah + aoff; const bf16* pAl = Al + aoff;
    const bf16* pBh = Bh + boff; const bf16* pBl = Bl + boff;

    extern __shared__ __align__(16) char dsm[];
    bf16* smem = (bf16*)dsm;
    const uint32_t sm_u32 = (uint32_t)__cvta_generic_to_shared(dsm);

    wmma::fragment<wmma::accumulator, 16, 16, 16, float> acc[2][4];
    #pragma unroll
    for (int i = 0; i < 2; i++)
        #pragma unroll
        for (int j = 0; j < 4; j++) wmma::fill_fragment(acc[i][j], 0.0f);

    const int NC = kLen >> 5;   // K chunks of 32  (always >= 4 here)

    const int lrow = tid >> 1;
    const int lseg = (tid & 1) * 2;

    // global->smem tile loads via cp.async.  MODE 2 loads only the B (V) tiles.
    auto load_chunk = [&](int buf, int ko) {
        const uint32_t b = sm_u32 + buf * CHUNK_E * 2;
        const uint32_t soff = (uint32_t)(lrow * TSTRIDE + lseg * 8) * 2;
        const bf16* srcs[4] = { pAh + ko, pAl + ko, pBh + ko, pBl + ko };
        const int lds[4] = { lda, lda, ldb, ldb };
        #pragma unroll
        for (int t = (MODE == 2 ? 2 : 0); t < 4; t++) {
            const bf16* g = srcs[t] + (size_t)lrow * lds[t] + lseg * 8;
            const uint32_t d = b + t * TILE_E * 2 + soff;
            cpa16(d, g);
            cpa16(d + 16, g + 8);
        }
    };

    // ---- MODE 2: on-the-fly P construction (scores -> exp -> hi/lo smem) ----
    const int pr = tid >> 1;            // row this thread fills
    const int pc = (tid & 1) * 16;      // 16-col segment
    float4 pre[4];
    float Mr = 0.f;
    const float* PSrow = nullptr;
    if (MODE == 2) {
        Mr = Mrow[h * SEQ + m0 + pr];
        PSrow = Cf + (size_t)h * SEQ * SEQ + (size_t)(m0 + pr) * lda + pc;  // lda = SEQ
    }
    auto loadP = [&](int c) {
        const float4* p = (const float4*)(PSrow + (c << 5));
        #pragma unroll
        for (int i = 0; i < 4; i++) pre[i] = p[i];
    };
    auto stsP = [&](int c) {
        const int k0 = c << 5;
        const int slim = m0 + pr;       // causal: t <= s
        float e[16];
        const float* pv = (const float*)pre;
        #pragma unroll
        for (int ii = 0; ii < 16; ii++) {
            const int t = k0 + pc + ii;
            e[ii] = (t <= slim) ? __expf(pv[ii] * SOFT_SCALE - Mr) : 0.f;
        }
        bf16* dh = smem + (c & 1) * CHUNK_E + pr * TSTRIDE + pc;
        bf16* dl = dh + TILE_E;
        bf16 hb[16], lb[16];
        #pragma unroll
        for (int ii = 0; ii < 16; ii++) {
            hb[ii] = __float2bfloat16(e[ii]);
            lb[ii] = __float2bfloat16(e[ii] - __bfloat162float(hb[ii]));
        }
        *(uint4*)dh = *(uint4*)&hb[0];  *(uint4*)(dh + 8) = *(uint4*)&hb[8];
        *(uint4*)dl = *(uint4*)&lb[0];  *(uint4*)(dl + 8) = *(uint4*)&lb[8];
    };

    if (MODE == 2) { loadP(0); stsP(0); loadP(1); }
    load_chunk(0, 0);
    CPA_COMMIT();

    for (int c = 0; c < NC; ++c) {
        if (c + 1 < NC) {
            if (MODE == 2) { stsP(c + 1); if (c + 2 < NC) loadP(c + 2); }
            load_chunk((c + 1) & 1, (c + 1) << 5);
            CPA_COMMIT();
            CPA_WAIT(1);
        } else {
            CPA_WAIT(0);
        }
        __syncthreads();

        const bf16* sb = smem + (c & 1) * CHUNK_E;
        const bf16* sAh = sb;
        const bf16* sAl = sb + TILE_E;
        const bf16* sBh = sb + 2 * TILE_E;
        const bf16* sBl = sb + 3 * TILE_E;

        #pragma unroll
        for (int kk = 0; kk < 32; kk += 16) {
            wmma::fragment<wmma::matrix_a, 16, 16, 16, bf16, wmma::row_major> ah[2], al[2];
            wmma::fragment<wmma::matrix_b, 16, 16, 16, bf16, wmma::col_major> bh[4], bl[4];
            #pragma unroll
            for (int i = 0; i < 2; i++) {
                wmma::load_matrix_sync(ah[i], sAh + (wm * 32 + i * 16) * TSTRIDE + kk, TSTRIDE);
                wmma::load_matrix_sync(al[i], sAl + (wm * 32 + i * 16) * TSTRIDE + kk, TSTRIDE);
            }
            #pragma unroll
            for (int j = 0; j < 4; j++) {
                wmma::load_matrix_sync(bh[j], sBh + (wn * 64 + j * 16) * TSTRIDE + kk, TSTRIDE);
                wmma::load_matrix_sync(bl[j], sBl + (wn * 64 + j * 16) * TSTRIDE + kk, TSTRIDE);
            }
            #pragma unroll
            for (int i = 0; i < 2; i++)
                #pragma unroll
                for (int j = 0; j < 4; j++) {
                    wmma::mma_sync(acc[i][j], ah[i], bh[j], acc[i][j]);
                    wmma::mma_sync(acc[i][j], ah[i], bl[j], acc[i][j]);
                    wmma::mma_sync(acc[i][j], al[i], bh[j], acc[i][j]);
                }
        }
        __syncthreads();
    }

    // ===================== epilogues =====================
    if (MODE == 0) {
        #pragma unroll
        for (int i = 0; i < 2; i++)
            #pragma unroll
            for (int j = 0; j < 4; j++)
                wmma::store_matrix_sync(Cf + (size_t)(m0 + wm * 32 + i * 16) * ldc + n0 + wn * 64 + j * 16,
                                        acc[i][j], ldc, wmma::mem_row_major);
    } else if (MODE == 1) {
        // stage, write fp32 scores, and emit per-tile row stats (max, sumexp)
        float* st = (float*)dsm;
        #pragma unroll
        for (int i = 0; i < 2; i++)
            #pragma unroll
            for (int j = 0; j < 4; j++)
                wmma::store_matrix_sync(st + (wm * 32 + i * 16) * SSTR + wn * 64 + j * 16,
                                        acc[i][j], SSTR, wmma::mem_row_major);
        __syncthreads();
        const int r = tid >> 1;
        const int c0 = (tid & 1) * 64;
        float* Crow = Cf + coff + (size_t)(m0 + r) * ldc + n0 + c0;
        #pragma unroll
        for (int cc = 0; cc < 64; cc += 4)
            *(float4*)(Crow + cc) = *(float4*)&st[r * SSTR + c0 + cc];
        // stats (masked for the diagonal tile)
        int vmax = 64;
        if (n0 == m0) { vmax = r - c0 + 1; vmax = vmax < 0 ? 0 : (vmax > 64 ? 64 : vmax); }
        float tm = -3.402823466e38f;
        for (int cc = 0; cc < vmax; cc++) tm = fmaxf(tm, st[r * SSTR + c0 + cc] * SOFT_SCALE);
        tm = fmaxf(tm, __shfl_xor_sync(0xffffffffu, tm, 1));
        float ts = 0.f;
        for (int cc = 0; cc < vmax; cc++) ts += __expf(st[r * SSTR + c0 + cc] * SOFT_SCALE - tm);
        ts += __shfl_xor_sync(0xffffffffu, ts, 1);
        if ((tid & 1) == 0) {
            const int idx = (h * 16 + (n0 >> 7)) * SEQ + m0 + r;
            Sm[idx] = tm;
            Ss[idx] = ts;
        }
    } else if (MODE == 2 || MODE == 3) {
        float* st = (float*)dsm;
        #pragma unroll
        for (int i = 0; i < 2; i++)
            #pragma unroll
            for (int j = 0; j < 4; j++)
                wmma::store_matrix_sync(st + (wm * 32 + i * 16) * SSTR + wn * 64 + j * 16,
                                        acc[i][j], SSTR, wmma::mem_row_major);
        __syncthreads();
        const int r = tid >> 1;
        const int c0 = (tid & 1) * 64;
        if (MODE == 2) {
            const float sc = Linv[h * SEQ + m0 + r];   // softmax normalization
            const size_t off = (size_t)(m0 + r) * ldc + (size_t)h * HD + c0;
            #pragma unroll
            for (int cc = 0; cc < 64; cc += 2)
                split2(st[r * SSTR + c0 + cc] * sc, st[r * SSTR + c0 + cc + 1] * sc,
                       Ch + off + cc, Cl + off + cc);
        } else {
            // RoPE: tile spans exactly one head (n0 % 128 == 0); pairs (2i, 2i+1)
            const float s_pos = (float)(m0 + r);
            const size_t off = (size_t)(m0 + r) * ldc + n0 + c0;
            #pragma unroll
            for (int cc = 0; cc < 64; cc += 2) {
                const int c = c0 + cc;
                const int i = c >> 1;
                float freq = __powf(500000.0f, -(float)i * (1.0f / 64.0f));
                float sn, cs; sincosf(s_pos * freq, &sn, &cs);
                float x0 = st[r * SSTR + c], x1 = st[r * SSTR + c + 1];
                split2(x0 * cs - x1 * sn, x0 * sn + x1 * cs, Ch + off + cc, Cl + off + cc);
            }
        }
    } else {
        // MODE 4: stage col-major (transpose), write vt[d, t] hi/lo
        float* st = (float*)dsm;
        #pragma unroll
        for (int i = 0; i < 2; i++)
            #pragma unroll
            for (int j = 0; j < 4; j++)
                wmma::store_matrix_sync(st + (wn * 64 + j * 16) * SSTR + wm * 32 + i * 16,
                                        acc[i][j], SSTR, wmma::mem_col_major);
        __syncthreads();
        const int d = tid >> 1;
        const int t0 = (tid & 1) * 64;
        const size_t off = (size_t)(n0 + d) * ldc + m0 + t0;
        #pragma unroll
        for (int tt = 0; tt < 64; tt += 2)
            split2(st[d * SSTR + t0 + tt], st[d * SSTR + t0 + tt + 1],
                   Ch + off + tt, Cl + off + tt);
    }
}

// ================= small kernels =================
// hi/lo split, 8 floats per thread-iter, 16B stores.
__global__ void split_kernel(const float4* __restrict__ s, uint4* __restrict__ h4,
                             uint4* __restrict__ l4, int n8) {
    const int i0 = blockIdx.x * 1024 + threadIdx.x;
    #pragma unroll
    for (int u = 0; u < 4; u++) {
        const int i = i0 + u * 256;
        if (i >= n8) return;
        float4 v0 = s[2 * i], v1 = s[2 * i + 1];
        float f[8] = { v0.x, v0.y, v0.z, v0.w, v1.x, v1.y, v1.z, v1.w };
        bf16 hb[8], lb[8];
        #pragma unroll
        for (int j = 0; j < 8; j++) {
            hb[j] = __float2bfloat16(f[j]);
            lb[j] = __float2bfloat16(f[j] - __bfloat162float(hb[j]));
        }
        h4[i] = *(uint4*)hb;
        l4[i] = *(uint4*)lb;
    }
}

// combine per-tile stats into global row max + 1/L.  One warp per (h, s).
__global__ void reduce_stats(const float* __restrict__ Sm, const float* __restrict__ Ss,
                             float* __restrict__ Mrow, float* __restrict__ linv) {
    const int w = threadIdx.x >> 5, lane = threadIdx.x & 31;
    const int s = blockIdx.x * 8 + w;
    const int h = blockIdx.y;
    const int jtmax = s >> 7;
    const float mj = (lane <= jtmax) ? Sm[(h * 16 + lane) * SEQ + s] : -3.402823466e38f;
    float M = mj;
    #pragma unroll
    for (int o = 16; o > 0; o >>= 1) M = fmaxf(M, __shfl_xor_sync(0xffffffffu, M, o));
    float l = (lane <= jtmax) ? Ss[(h * 16 + lane) * SEQ + s] * __expf(mj - M) : 0.f;
    #pragma unroll
    for (int o = 16; o > 0; o >>= 1) l += __shfl_xor_sync(0xffffffffu, l, o);
    if (lane == 0) {
        Mrow[h * SEQ + s] = M;
        linv[h * SEQ + s] = 1.0f / l;
    }
}

// ================= host =================
extern "C" void kernel_launch(void* const* d_in, const int* in_sizes, int n_in,
                              void* d_out, int out_size) {
    (void)in_sizes; (void)n_in; (void)out_size;
    const float* x  = (const float*)d_in[0];
    const float* wq = (const float*)d_in[1];
    const float* wk = (const float*)d_in[2];
    const float* wv = (const float*)d_in[3];
    const float* wo = (const float*)d_in[4];
    float* out = (float*)d_out;

    float *scores, *statm, *stats, *rowM, *linv;
    bf16 *xh, *xl, *wqh, *wql, *wkh, *wkl, *wvh, *wvl, *woh, *wol;
    bf16 *qh, *ql, *kh, *kl, *vth, *vtl, *ah, *al;
    cudaGetSymbolAddress((void**)&scores, g_scores);
    cudaGetSymbolAddress((void**)&statm, g_stat_m);
    cudaGetSymbolAddress((void**)&stats, g_stat_s);
    cudaGetSymbolAddress((void**)&rowM, g_rowM);
    cudaGetSymbolAddress((void**)&linv, g_linv);
    cudaGetSymbolAddress((void**)&xh, g_xh);  cudaGetSymbolAddress((void**)&xl, g_xl);
    cudaGetSymbolAddress((void**)&wqh, g_wqh); cudaGetSymbolAddress((void**)&wql, g_wql);
    cudaGetSymbolAddress((void**)&wkh, g_wkh); cudaGetSymbolAddress((void**)&wkl, g_wkl);
    cudaGetSymbolAddress((void**)&wvh, g_wvh); cudaGetSymbolAddress((void**)&wvl, g_wvl);
    cudaGetSymbolAddress((void**)&woh, g_woh); cudaGetSymbolAddress((void**)&wol, g_wol);
    cudaGetSymbolAddress((void**)&qh, g_qh);  cudaGetSymbolAddress((void**)&ql, g_ql);
    cudaGetSymbolAddress((void**)&kh, g_kh);  cudaGetSymbolAddress((void**)&kl, g_kl);
    cudaGetSymbolAddress((void**)&vth, g_vth); cudaGetSymbolAddress((void**)&vtl, g_vtl);
    cudaGetSymbolAddress((void**)&ah, g_ah);  cudaGetSymbolAddress((void**)&al, g_al);

    cudaFuncSetAttribute(gemm3_kernel<0>, cudaFuncAttributeMaxDynamicSharedMemorySize, GSMEM);
    cudaFuncSetAttribute(gemm3_kernel<1>, cudaFuncAttributeMaxDynamicSharedMemorySize, GSMEM);
    cudaFuncSetAttribute(gemm3_kernel<2>, cudaFuncAttributeMaxDynamicSharedMemorySize, GSMEM);
    cudaFuncSetAttribute(gemm3_kernel<3>, cudaFuncAttributeMaxDynamicSharedMemorySize, GSMEM);
    cudaFuncSetAttribute(gemm3_kernel<4>, cudaFuncAttributeMaxDynamicSharedMemorySize, GSMEM);

    // split inputs to bf16 hi/lo  (n8 = floats/8)
    split_kernel<<<SEQ*DIM/8/1024, 256>>>((const float4*)x,  (uint4*)xh,  (uint4*)xl,  SEQ*DIM/8);
    split_kernel<<<DIM*DIM/8/1024, 256>>>((const float4*)wq, (uint4*)wqh, (uint4*)wql, DIM*DIM/8);
    split_kernel<<<KVD*DIM/8/1024, 256>>>((const float4*)wk, (uint4*)wkh, (uint4*)wkl, KVD*DIM/8);
    split_kernel<<<KVD*DIM/8/1024, 256>>>((const float4*)wv, (uint4*)wvh, (uint4*)wvl, KVD*DIM/8);
    split_kernel<<<DIM*DIM/8/1024, 256>>>((const float4*)wo, (uint4*)woh, (uint4*)wol, DIM*DIM/8);

    // projections with fused epilogues (RoPE for Q/K, transpose for V)
    gemm3_kernel<3><<<dim3(DIM/128, SEQ/128), 256, GSMEM>>>(xh, xl, wqh, wql, nullptr, qh, ql, nullptr, nullptr, nullptr, nullptr, DIM, DIM, DIM, DIM);
    gemm3_kernel<3><<<dim3(KVD/128, SEQ/128), 256, GSMEM>>>(xh, xl, wkh, wkl, nullptr, kh, kl, nullptr, nullptr, nullptr, nullptr, DIM, DIM, DIM, KVD);
    gemm3_kernel<4><<<dim3(KVD/128, SEQ/128), 256, GSMEM>>>(xh, xl, wvh, wvl, nullptr, vth, vtl, nullptr, nullptr, nullptr, nullptr, DIM, DIM, DIM, SEQ);

    // attention: scores(+stats) -> tiny reduce -> PV with inline exp
    gemm3_kernel<1><<<dim3(136, 1, NH), 256, GSMEM>>>(qh, ql, kh, kl, scores, nullptr, nullptr, nullptr, nullptr, statm, stats, HD, DIM, KVD, SEQ);
    reduce_stats<<<dim3(SEQ/8, NH), 256>>>(statm, stats, rowM, linv);
    gemm3_kernel<2><<<dim3(1, SEQ/128, NH), 256, GSMEM>>>(nullptr, nullptr, vth, vtl, scores, ah, al, linv, rowM, nullptr, nullptr, 0, SEQ, SEQ, DIM);

    // output projection
    gemm3_kernel<0><<<dim3(DIM/128, SEQ/128), 256, GSMEM>>>(ah, al, woh, wol, out, nullptr, nullptr, nullptr, nullptr, nullptr, nullptr, DIM, DIM, DIM, DIM);
}

// round 13
// speedup vs baseline: 1.1025x; 1.1025x over previous
#include <cuda_runtime.h>
#include <cuda_bf16.h>
#include <mma.h>
#include <stdint.h>
#include <math.h>

using namespace nvcuda;

#define SEQ 2048
#define DIM 4096
#define NH 32
#define NKV 8
#define HD 128
#define KVD (NKV*HD)   // 1024

typedef __nv_bfloat16 bf16;

// ================= scratch (no cudaMalloc allowed) =================
__device__ float g_scores[(size_t)NH * SEQ * SEQ];              // 512 MB
__device__ float g_linv[NH * SEQ];                              // per-row 1/sum
__device__ bf16 g_xh[SEQ * DIM],  g_xl[SEQ * DIM];
__device__ bf16 g_wqh[DIM * DIM], g_wql[DIM * DIM];
__device__ bf16 g_wkh[KVD * DIM], g_wkl[KVD * DIM];
__device__ bf16 g_wvh[KVD * DIM], g_wvl[KVD * DIM];
__device__ bf16 g_woh[DIM * DIM], g_wol[DIM * DIM];
__device__ bf16 g_qh[SEQ * DIM],  g_ql[SEQ * DIM];
__device__ bf16 g_kh[SEQ * KVD],  g_kl[SEQ * KVD];
__device__ bf16 g_vth[KVD * SEQ], g_vtl[KVD * SEQ];             // V transposed [d, t]
__device__ bf16 g_ph[(size_t)NH * SEQ * SEQ], g_pl[(size_t)NH * SEQ * SEQ];
__device__ bf16 g_ah[SEQ * DIM],  g_al[SEQ * DIM];

#define SOFT_SCALE 0.08838834764831845f   // 1/sqrt(128)

// ================= cp.async helpers =================
__device__ __forceinline__ void cpa16(uint32_t dst, const void* src) {
    unsigned long long g = (unsigned long long)__cvta_generic_to_global(src);
    asm volatile("cp.async.cg.shared.global [%0], [%1], 16;" :: "r"(dst), "l"(g) : "memory");
}
#define CPA_COMMIT() asm volatile("cp.async.commit_group;" ::: "memory")
#define CPA_WAIT(n)  asm volatile("cp.async.wait_group %0;" :: "n"(n) : "memory")

__device__ __forceinline__ void split2(float v0, float v1, bf16* ph, bf16* pl) {
    bf16 h0 = __float2bfloat16(v0), h1 = __float2bfloat16(v1);
    bf16 l0 = __float2bfloat16(v0 - __bfloat162float(h0));
    bf16 l1 = __float2bfloat16(v1 - __bfloat162float(h1));
    *(__nv_bfloat162*)ph = __halves2bfloat162(h0, h1);
    *(__nv_bfloat162*)pl = __halves2bfloat162(l0, l1);
}

// ================= 3-pass bf16 HMMA GEMM =================
// C[M,N] = Ah*Bh^T + Ah*Bl^T + Al*Bh^T   (TN, row-major, 128x128 CTA tiles)
// MODE 0: generic fp32 C.
// MODE 1: scores (per-head, triangular grid), fp32 C.
// MODE 2: PV (per-head, K truncated at diagonal, reversed m order,
//         per-row 1/l normalization), bf16 hi/lo C.
// MODE 3: projection + RoPE + bf16 hi/lo C (Q and K projections).
// MODE 4: projection + transpose + bf16 hi/lo C (V projection).
//
// smem: DOUBLE-buffered chunks of K=32.  Each chunk holds 4 tiles
// (Ah, Al, Bh, Bl), each 128 rows x 32 bf16 with row stride 40 (80B).
// Inner loop runs as 3 sequential passes (hh, hl, lh) to keep register
// liveness low enough for 2 CTAs/SM (__launch_bounds__(256, 2)).
#define TSTRIDE 40
#define TILE_E  (128 * TSTRIDE)          // 5120 elements per tile
#define CHUNK_E (4 * TILE_E)             // 20480 elements per buffer (40KB)
#define GSMEM   (2 * CHUNK_E * 2)        // 81920 bytes (>= 67584 staging)
#define SSTR    132                      // fp32 staging stride

template<int MODE>
__global__ void __launch_bounds__(256, 2) gemm3_kernel(
    const bf16* __restrict__ Ah, const bf16* __restrict__ Al,
    const bf16* __restrict__ Bh, const bf16* __restrict__ Bl,
    float* __restrict__ Cf, bf16* __restrict__ Ch, bf16* __restrict__ Cl,
    const float* __restrict__ Linv,
    int K, int lda, int ldb, int ldc)
{
    int m0, n0;
    if (MODE == 1) {
        // triangular decode: blockIdx.x in [0, 136)
        const int L = blockIdx.x;
        int s0i = (int)((sqrtf(8.0f * (float)L + 1.0f) - 1.0f) * 0.5f);
        while ((s0i + 1) * (s0i + 2) / 2 <= L) s0i++;
        while (s0i * (s0i + 1) / 2 > L) s0i--;
        m0 = s0i * 128;
        n0 = (L - s0i * (s0i + 1) / 2) * 128;
    } else if (MODE == 2) {
        m0 = (int)(gridDim.y - 1 - blockIdx.y) * 128;   // heavy tiles first
        n0 = blockIdx.x * 128;
    } else {
        m0 = blockIdx.y * 128;
        n0 = blockIdx.x * 128;
    }
    const int h = blockIdx.z, kvh = h >> 2;
    const int tid = threadIdx.x;
    const int warp = tid >> 5;
    const int wm = warp >> 1;           // 0..3  (32-row slice)
    const int wn = warp & 1;            // 0..1  (64-col slice)

    size_t aoff, boff, coff = 0;
    int kLen = K;
    if (MODE == 1)      { aoff = (size_t)m0 * lda + (size_t)h * HD;        boff = (size_t)n0 * ldb + (size_t)kvh * HD;
                          coff = (size_t)h * SEQ * SEQ; }
    else if (MODE == 2) { aoff = (size_t)h * SEQ * SEQ + (size_t)m0 * lda; boff = (size_t)(kvh * HD) * ldb;
                          kLen = m0 + 128; }
    else                { aoff = (size_t)m0 * lda;                         boff = (size_t)n0 * ldb; }
    const bf16* pAh = Ah + aoff; const bf16* pAl = Al + aoff;
    const bf16* pBh = Bh + boff; const bf16* pBl = Bl + boff;

    extern __shared__ __align__(16) char dsm[];
    bf16* smem = (bf16*)dsm;
    const uint32_t sm_u32 = (uint32_t)__cvta_generic_to_shared(dsm);

    wmma::fragment<wmma::accumulator, 16, 16, 16, float> acc[2][4];
    #pragma unroll
    for (int i = 0; i < 2; i++)
        #pragma unroll
        for (int j = 0; j < 4; j++) wmma::fill_fragment(acc[i][j], 0.0f);

    const int NC = kLen >> 5;   // K chunks of 32  (always >= 4 here)

    const int lrow = tid >> 1;
    const int lseg = (tid & 1) * 2;

    auto load_chunk = [&](int buf, int ko) {
        const uint32_t b = sm_u32 + buf * CHUNK_E * 2;
        const uint32_t soff = (uint32_t)(lrow * TSTRIDE + lseg * 8) * 2;
        const bf16* srcs[4] = { pAh + ko, pAl + ko, pBh + ko, pBl + ko };
        const int lds[4] = { lda, lda, ldb, ldb };
        #pragma unroll
        for (int t = 0; t < 4; t++) {
            const bf16* g = srcs[t] + (size_t)lrow * lds[t] + lseg * 8;
            const uint32_t d = b + t * TILE_E * 2 + soff;
            cpa16(d, g);
            cpa16(d + 16, g + 8);
        }
    };

    load_chunk(0, 0);
    CPA_COMMIT();

    for (int c = 0; c < NC; ++c) {
        if (c + 1 < NC) {
            load_chunk((c + 1) & 1, (c + 1) << 5);
            CPA_COMMIT();
            CPA_WAIT(1);
        } else {
            CPA_WAIT(0);
        }
        __syncthreads();

        const bf16* sb = smem + (c & 1) * CHUNK_E;
        const bf16* sAh = sb;
        const bf16* sAl = sb + TILE_E;
        const bf16* sBh = sb + 2 * TILE_E;
        const bf16* sBl = sb + 3 * TILE_E;

        // three low-liveness passes: Ah*Bh, Ah*Bl, Al*Bh
        #pragma unroll
        for (int p = 0; p < 3; p++) {
            const bf16* sa = (p == 2) ? sAl : sAh;
            const bf16* sbb = (p == 1) ? sBl : sBh;
            #pragma unroll
            for (int kk = 0; kk < 32; kk += 16) {
                wmma::fragment<wmma::matrix_a, 16, 16, 16, bf16, wmma::row_major> af[2];
                wmma::fragment<wmma::matrix_b, 16, 16, 16, bf16, wmma::col_major> bfr[4];
                #pragma unroll
                for (int i = 0; i < 2; i++)
                    wmma::load_matrix_sync(af[i], sa + (wm * 32 + i * 16) * TSTRIDE + kk, TSTRIDE);
                #pragma unroll
                for (int j = 0; j < 4; j++)
                    wmma::load_matrix_sync(bfr[j], sbb + (wn * 64 + j * 16) * TSTRIDE + kk, TSTRIDE);
                #pragma unroll
                for (int i = 0; i < 2; i++)
                    #pragma unroll
                    for (int j = 0; j < 4; j++)
                        wmma::mma_sync(acc[i][j], af[i], bfr[j], acc[i][j]);
            }
        }
        __syncthreads();
    }

    // ===================== epilogues =====================
    if (MODE == 0 || MODE == 1) {
        float* C = Cf + coff;
        #pragma unroll
        for (int i = 0; i < 2; i++)
            #pragma unroll
            for (int j = 0; j < 4; j++)
                wmma::store_matrix_sync(C + (size_t)(m0 + wm * 32 + i * 16) * ldc + n0 + wn * 64 + j * 16,
                                        acc[i][j], ldc, wmma::mem_row_major);
    } else if (MODE == 2 || MODE == 3) {
        float* st = (float*)dsm;
        #pragma unroll
        for (int i = 0; i < 2; i++)
            #pragma unroll
            for (int j = 0; j < 4; j++)
                wmma::store_matrix_sync(st + (wm * 32 + i * 16) * SSTR + wn * 64 + j * 16,
                                        acc[i][j], SSTR, wmma::mem_row_major);
        __syncthreads();
        const int r = tid >> 1;
        const int c0 = (tid & 1) * 64;
        if (MODE == 2) {
            const float sc = Linv[h * SEQ + m0 + r];   // fold softmax normalization here
            const size_t off = (size_t)(m0 + r) * ldc + (size_t)h * HD + c0;
            #pragma unroll
            for (int cc = 0; cc < 64; cc += 2)
                split2(st[r * SSTR + c0 + cc] * sc, st[r * SSTR + c0 + cc + 1] * sc,
                       Ch + off + cc, Cl + off + cc);
        } else {
            // RoPE: tile spans exactly one head (n0 % 128 == 0); pairs (2i, 2i+1)
            const float s_pos = (float)(m0 + r);
            const size_t off = (size_t)(m0 + r) * ldc + n0 + c0;
            #pragma unroll
            for (int cc = 0; cc < 64; cc += 2) {
                const int c = c0 + cc;
                const int i = c >> 1;
                float freq = __powf(500000.0f, -(float)i * (1.0f / 64.0f));
                float sn, cs; sincosf(s_pos * freq, &sn, &cs);
                float x0 = st[r * SSTR + c], x1 = st[r * SSTR + c + 1];
                split2(x0 * cs - x1 * sn, x0 * sn + x1 * cs, Ch + off + cc, Cl + off + cc);
            }
        }
    } else {
        // MODE 4: stage col-major (transpose), write vt[d, t] hi/lo
        float* st = (float*)dsm;
        #pragma unroll
        for (int i = 0; i < 2; i++)
            #pragma unroll
            for (int j = 0; j < 4; j++)
                wmma::store_matrix_sync(st + (wn * 64 + j * 16) * SSTR + wm * 32 + i * 16,
                                        acc[i][j], SSTR, wmma::mem_col_major);
        __syncthreads();
        const int d = tid >> 1;
        const int t0 = (tid & 1) * 64;
        const size_t off = (size_t)(n0 + d) * ldc + m0 + t0;
        #pragma unroll
        for (int tt = 0; tt < 64; tt += 2)
            split2(st[d * SSTR + t0 + tt], st[d * SSTR + t0 + tt + 1],
                   Ch + off + tt, Cl + off + tt);
    }
}

// ================= small kernels =================
// hi/lo split, 8 floats per thread-iter, 16B stores.
__global__ void split_kernel(const float4* __restrict__ s, uint4* __restrict__ h4,
                             uint4* __restrict__ l4, int n8) {
    const int i0 = blockIdx.x * 1024 + threadIdx.x;
    #pragma unroll
    for (int u = 0; u < 4; u++) {
        const int i = i0 + u * 256;
        if (i >= n8) return;
        float4 v0 = s[2 * i], v1 = s[2 * i + 1];
        float f[8] = { v0.x, v0.y, v0.z, v0.w, v1.x, v1.y, v1.z, v1.w };
        bf16 hb[8], lb[8];
        #pragma unroll
        for (int j = 0; j < 8; j++) {
            hb[j] = __float2bfloat16(f[j]);
            lb[j] = __float2bfloat16(f[j] - __bfloat162float(hb[j]));
        }
        h4[i] = *(uint4*)hb;
        l4[i] = *(uint4*)lb;
    }
}

// warp-per-row softmax, EXP-ONCE: caches the scaled row in smem, computes max,
// then a single exp pass writing UNNORMALIZED e-values (bf16 hi/lo) and 1/sum.
// Tail zeroed to the next 128 boundary so PV runs a truncated plain GEMM.
// PV epilogue multiplies rows by linv.
__global__ void softmax_kernel(const float* __restrict__ scores, bf16* __restrict__ ph,
                               bf16* __restrict__ pl, float* __restrict__ linv) {
    extern __shared__ float cache[];   // 8 warps x 2048 floats = 64KB
    const int warp = threadIdx.x >> 5, lane = threadIdx.x & 31;
    const int s = blockIdx.x * 8 + warp;
    const int h = blockIdx.y;
    const float* row = scores + ((size_t)h * SEQ + s) * SEQ;
    bf16* prh = ph + ((size_t)h * SEQ + s) * SEQ;
    bf16* prl = pl + ((size_t)h * SEQ + s) * SEQ;
    float* cr = cache + warp * SEQ;
    const int len = s + 1;
    const int zlen = ((s >> 7) + 1) << 7;

    float mx = -3.402823466e38f;
    for (int t = lane; t < len; t += 32) {
        float v = row[t] * SOFT_SCALE;
        cr[t] = v;
        mx = fmaxf(mx, v);
    }
    #pragma unroll
    for (int o = 16; o > 0; o >>= 1) mx = fmaxf(mx, __shfl_xor_sync(0xffffffffu, mx, o));

    float sum = 0.f;
    for (int t = lane; t < len; t += 32) {
        float e = __expf(cr[t] - mx);
        sum += e;
        bf16 hh = __float2bfloat16(e);
        prh[t] = hh;
        prl[t] = __float2bfloat16(e - __bfloat162float(hh));
    }
    #pragma unroll
    for (int o = 16; o > 0; o >>= 1) sum += __shfl_xor_sync(0xffffffffu, sum, o);
    if (lane == 0) linv[h * SEQ + s] = 1.0f / sum;

    const bf16 z = __float2bfloat16(0.f);
    for (int t = len + lane; t < zlen; t += 32) { prh[t] = z; prl[t] = z; }
}

// ================= host =================
extern "C" void kernel_launch(void* const* d_in, const int* in_sizes, int n_in,
                              void* d_out, int out_size) {
    (void)in_sizes; (void)n_in; (void)out_size;
    const float* x  = (const float*)d_in[0];
    const float* wq = (const float*)d_in[1];
    const float* wk = (const float*)d_in[2];
    const float* wv = (const float*)d_in[3];
    const float* wo = (const float*)d_in[4];
    float* out = (float*)d_out;

    float *scores, *linv;
    bf16 *xh, *xl, *wqh, *wql, *wkh, *wkl, *wvh, *wvl, *woh, *wol;
    bf16 *qh, *ql, *kh, *kl, *vth, *vtl, *ph, *pl, *ah, *al;
    cudaGetSymbolAddress((void**)&scores, g_scores);
    cudaGetSymbolAddress((void**)&linv, g_linv);
    cudaGetSymbolAddress((void**)&xh, g_xh);  cudaGetSymbolAddress((void**)&xl, g_xl);
    cudaGetSymbolAddress((void**)&wqh, g_wqh); cudaGetSymbolAddress((void**)&wql, g_wql);
    cudaGetSymbolAddress((void**)&wkh, g_wkh); cudaGetSymbolAddress((void**)&wkl, g_wkl);
    cudaGetSymbolAddress((void**)&wvh, g_wvh); cudaGetSymbolAddress((void**)&wvl, g_wvl);
    cudaGetSymbolAddress((void**)&woh, g_woh); cudaGetSymbolAddress((void**)&wol, g_wol);
    cudaGetSymbolAddress((void**)&qh, g_qh);  cudaGetSymbolAddress((void**)&ql, g_ql);
    cudaGetSymbolAddress((void**)&kh, g_kh);  cudaGetSymbolAddress((void**)&kl, g_kl);
    cudaGetSymbolAddress((void**)&vth, g_vth); cudaGetSymbolAddress((void**)&vtl, g_vtl);
    cudaGetSymbolAddress((void**)&ph, g_ph);  cudaGetSymbolAddress((void**)&pl, g_pl);
    cudaGetSymbolAddress((void**)&ah, g_ah);  cudaGetSymbolAddress((void**)&al, g_al);

    cudaFuncSetAttribute(gemm3_kernel<0>, cudaFuncAttributeMaxDynamicSharedMemorySize, GSMEM);
    cudaFuncSetAttribute(gemm3_kernel<1>, cudaFuncAttributeMaxDynamicSharedMemorySize, GSMEM);
    cudaFuncSetAttribute(gemm3_kernel<2>, cudaFuncAttributeMaxDynamicSharedMemorySize, GSMEM);
    cudaFuncSetAttribute(gemm3_kernel<3>, cudaFuncAttributeMaxDynamicSharedMemorySize, GSMEM);
    cudaFuncSetAttribute(gemm3_kernel<4>, cudaFuncAttributeMaxDynamicSharedMemorySize, GSMEM);
    cudaFuncSetAttribute(softmax_kernel, cudaFuncAttributeMaxDynamicSharedMemorySize, 8 * SEQ * 4);

    // split inputs to bf16 hi/lo  (n8 = floats/8)
    split_kernel<<<SEQ*DIM/8/1024, 256>>>((const float4*)x,  (uint4*)xh,  (uint4*)xl,  SEQ*DIM/8);
    split_kernel<<<DIM*DIM/8/1024, 256>>>((const float4*)wq, (uint4*)wqh, (uint4*)wql, DIM*DIM/8);
    split_kernel<<<KVD*DIM/8/1024, 256>>>((const float4*)wk, (uint4*)wkh, (uint4*)wkl, KVD*DIM/8);
    split_kernel<<<KVD*DIM/8/1024, 256>>>((const float4*)wv, (uint4*)wvh, (uint4*)wvl, KVD*DIM/8);
    split_kernel<<<DIM*DIM/8/1024, 256>>>((const float4*)wo, (uint4*)woh, (uint4*)wol, DIM*DIM/8);

    // projections with fused epilogues (RoPE for Q/K, transpose for V)
    gemm3_kernel<3><<<dim3(DIM/128, SEQ/128), 256, GSMEM>>>(xh, xl, wqh, wql, nullptr, qh, ql, nullptr, DIM, DIM, DIM, DIM);
    gemm3_kernel<3><<<dim3(KVD/128, SEQ/128), 256, GSMEM>>>(xh, xl, wkh, wkl, nullptr, kh, kl, nullptr, DIM, DIM, DIM, KVD);
    gemm3_kernel<4><<<dim3(KVD/128, SEQ/128), 256, GSMEM>>>(xh, xl, wvh, wvl, nullptr, vth, vtl, nullptr, DIM, DIM, DIM, SEQ);

    // attention
    gemm3_kernel<1><<<dim3(136, 1, NH), 256, GSMEM>>>(qh, ql, kh, kl, scores, nullptr, nullptr, nullptr, HD, DIM, KVD, SEQ);
    softmax_kernel<<<dim3(SEQ/8, NH), 256, 8*SEQ*4>>>(scores, ph, pl, linv);
    gemm3_kernel<2><<<dim3(1, SEQ/128, NH), 256, GSMEM>>>(ph, pl, vth, vtl, nullptr, ah, al, linv, 0, SEQ, SEQ, DIM);

    // output projection
    gemm3_kernel<0><<<dim3(DIM/128, SEQ/128), 256, GSMEM>>>(ah, al, woh, wol, out, nullptr, nullptr, nullptr, DIM, DIM, DIM, DIM);
}

// round 14
// speedup vs baseline: 1.1121x; 1.0087x over previous
#include <cuda_runtime.h>
#include <cuda_bf16.h>
#include <mma.h>
#include <stdint.h>
#include <math.h>

using namespace nvcuda;

#define SEQ 2048
#define DIM 4096
#define NH 32
#define NKV 8
#define HD 128
#define KVD (NKV*HD)   // 1024

typedef __nv_bfloat16 bf16;

// ================= scratch (no cudaMalloc allowed) =================
__device__ float g_scores[(size_t)NH * SEQ * SEQ];              // 512 MB
__device__ float g_linv[NH * SEQ];                              // per-row 1/sum
__device__ bf16 g_xh[SEQ * DIM],  g_xl[SEQ * DIM];
__device__ bf16 g_wqh[DIM * DIM], g_wql[DIM * DIM];
__device__ bf16 g_wkh[KVD * DIM], g_wkl[KVD * DIM];
__device__ bf16 g_wvh[KVD * DIM], g_wvl[KVD * DIM];
__device__ bf16 g_woh[DIM * DIM], g_wol[DIM * DIM];
__device__ bf16 g_qh[SEQ * DIM],  g_ql[SEQ * DIM];
__device__ bf16 g_kh[SEQ * KVD],  g_kl[SEQ * KVD];
__device__ bf16 g_vth[KVD * SEQ], g_vtl[KVD * SEQ];             // V transposed [d, t]
__device__ bf16 g_ph[(size_t)NH * SEQ * SEQ], g_pl[(size_t)NH * SEQ * SEQ];
__device__ bf16 g_ah[SEQ * DIM],  g_al[SEQ * DIM];

#define SOFT_SCALE 0.08838834764831845f   // 1/sqrt(128)

// ================= cp.async helpers =================
__device__ __forceinline__ void cpa16(uint32_t dst, const void* src) {
    unsigned long long g = (unsigned long long)__cvta_generic_to_global(src);
    asm volatile("cp.async.cg.shared.global [%0], [%1], 16;" :: "r"(dst), "l"(g) : "memory");
}
#define CPA_COMMIT() asm volatile("cp.async.commit_group;" ::: "memory")
#define CPA_WAIT(n)  asm volatile("cp.async.wait_group %0;" :: "n"(n) : "memory")

__device__ __forceinline__ void split2(float v0, float v1, bf16* ph, bf16* pl) {
    bf16 h0 = __float2bfloat16(v0), h1 = __float2bfloat16(v1);
    bf16 l0 = __float2bfloat16(v0 - __bfloat162float(h0));
    bf16 l1 = __float2bfloat16(v1 - __bfloat162float(h1));
    *(__nv_bfloat162*)ph = __halves2bfloat162(h0, h1);
    *(__nv_bfloat162*)pl = __halves2bfloat162(l0, l1);
}

#define TSTRIDE 40
#define TILE_E  (128 * TSTRIDE)          // 5120 elements per tile
#define CHUNK_E (4 * TILE_E)             // 20480 elements per buffer (40KB)
#define GSMEM   (2 * CHUNK_E * 2)        // 81920 bytes (>= 67584 staging)
#define SSTR    132                      // fp32 staging stride

// ===== shared GEMM mainloop: 3-pass bf16 HMMA, double-buffered cp.async =====
// Computes acc += Ah*Bh^T + Ah*Bl^T + Al*Bh^T over kLen (TN, 128x128 tile).
#define GEMM3_BODY(pAh_, pAl_, pBh_, pBl_, lda_, ldb_, kLen_)                          \
    wmma::fragment<wmma::accumulator, 16, 16, 16, float> acc[2][4];                    \
    _Pragma("unroll")                                                                  \
    for (int i = 0; i < 2; i++)                                                        \
        _Pragma("unroll")                                                              \
        for (int j = 0; j < 4; j++) wmma::fill_fragment(acc[i][j], 0.0f);              \
    const int NC = (kLen_) >> 5;                                                       \
    const int lrow = tid >> 1;                                                         \
    const int lseg = (tid & 1) * 2;                                                    \
    auto load_chunk = [&](int buf, int ko) {                                           \
        const uint32_t b = sm_u32 + buf * CHUNK_E * 2;                                 \
        const uint32_t soff = (uint32_t)(lrow * TSTRIDE + lseg * 8) * 2;               \
        const bf16* srcs[4] = { (pAh_) + ko, (pAl_) + ko, (pBh_) + ko, (pBl_) + ko };  \
        const int lds[4] = { (lda_), (lda_), (ldb_), (ldb_) };                         \
        _Pragma("unroll")                                                              \
        for (int t = 0; t < 4; t++) {                                                  \
            const bf16* g = srcs[t] + (size_t)lrow * lds[t] + lseg * 8;                \
            const uint32_t d = b + t * TILE_E * 2 + soff;                              \
            cpa16(d, g);                                                               \
            cpa16(d + 16, g + 8);                                                      \
        }                                                                              \
    };                                                                                 \
    load_chunk(0, 0);                                                                  \
    CPA_COMMIT();                                                                      \
    for (int c = 0; c < NC; ++c) {                                                     \
        if (c + 1 < NC) {                                                              \
            load_chunk((c + 1) & 1, (c + 1) << 5);                                     \
            CPA_COMMIT();                                                              \
            CPA_WAIT(1);                                                               \
        } else {                                                                       \
            CPA_WAIT(0);                                                               \
        }                                                                              \
        __syncthreads();                                                               \
        const bf16* sb = smem + (c & 1) * CHUNK_E;                                     \
        _Pragma("unroll")                                                              \
        for (int p = 0; p < 3; p++) {                                                  \
            const bf16* sa  = (p == 2) ? sb + TILE_E     : sb;                         \
            const bf16* sbb = (p == 1) ? sb + 3 * TILE_E : sb + 2 * TILE_E;            \
            _Pragma("unroll")                                                          \
            for (int kk = 0; kk < 32; kk += 16) {                                      \
                wmma::fragment<wmma::matrix_a, 16, 16, 16, bf16, wmma::row_major> af[2]; \
                wmma::fragment<wmma::matrix_b, 16, 16, 16, bf16, wmma::col_major> bfr[4]; \
                _Pragma("unroll")                                                      \
                for (int i = 0; i < 2; i++)                                            \
                    wmma::load_matrix_sync(af[i], sa + (wm * 32 + i * 16) * TSTRIDE + kk, TSTRIDE); \
                _Pragma("unroll")                                                      \
                for (int j = 0; j < 4; j++)                                            \
                    wmma::load_matrix_sync(bfr[j], sbb + (wn * 64 + j * 16) * TSTRIDE + kk, TSTRIDE); \
                _Pragma("unroll")                                                      \
                for (int i = 0; i < 2; i++)                                            \
                    _Pragma("unroll")                                                  \
                    for (int j = 0; j < 4; j++)                                        \
                        wmma::mma_sync(acc[i][j], af[i], bfr[j], acc[i][j]);           \
            }                                                                          \
        }                                                                              \
        __syncthreads();                                                               \
    }

// ================= fused QKV projection kernel =================
// 768 CTAs: [0,512) Q tiles (+RoPE), [512,640) K tiles (+RoPE),
// [640,768) V tiles (+transpose).  All read xh/xl; B operand per range.
__global__ void __launch_bounds__(256, 2) qkv_kernel() {
    const int bid = blockIdx.x;
    const int tid = threadIdx.x;
    const int warp = tid >> 5;
    const int wm = warp >> 1;
    const int wn = warp & 1;

    int m0, n0, sel;
    const bf16 *Bh_, *Bl_;
    if (bid < 512)      { sel = 0; m0 = (bid >> 5) * 128; n0 = (bid & 31) * 128; Bh_ = g_wqh; Bl_ = g_wql; }
    else if (bid < 640) { int t = bid - 512; sel = 1; m0 = (t >> 3) * 128; n0 = (t & 7) * 128; Bh_ = g_wkh; Bl_ = g_wkl; }
    else                { int t = bid - 640; sel = 2; m0 = (t >> 3) * 128; n0 = (t & 7) * 128; Bh_ = g_wvh; Bl_ = g_wvl; }

    const bf16* pAh = g_xh + (size_t)m0 * DIM;
    const bf16* pAl = g_xl + (size_t)m0 * DIM;
    const bf16* pBh = Bh_ + (size_t)n0 * DIM;
    const bf16* pBl = Bl_ + (size_t)n0 * DIM;

    extern __shared__ __align__(16) char dsm[];
    bf16* smem = (bf16*)dsm;
    const uint32_t sm_u32 = (uint32_t)__cvta_generic_to_shared(dsm);

    GEMM3_BODY(pAh, pAl, pBh, pBl, DIM, DIM, DIM)

    float* st = (float*)dsm;
    if (sel < 2) {
        // RoPE + hi/lo split (tile spans exactly one head)
        #pragma unroll
        for (int i = 0; i < 2; i++)
            #pragma unroll
            for (int j = 0; j < 4; j++)
                wmma::store_matrix_sync(st + (wm * 32 + i * 16) * SSTR + wn * 64 + j * 16,
                                        acc[i][j], SSTR, wmma::mem_row_major);
        __syncthreads();
        const int r = tid >> 1;
        const int c0 = (tid & 1) * 64;
        bf16* Ch = (sel == 0) ? g_qh : g_kh;
        bf16* Cl = (sel == 0) ? g_ql : g_kl;
        const int ldc = (sel == 0) ? DIM : KVD;
        const float s_pos = (float)(m0 + r);
        const size_t off = (size_t)(m0 + r) * ldc + n0 + c0;
        #pragma unroll
        for (int cc = 0; cc < 64; cc += 2) {
            const int c = c0 + cc;
            const int i = c >> 1;
            float freq = __powf(500000.0f, -(float)i * (1.0f / 64.0f));
            float sn, cs; sincosf(s_pos * freq, &sn, &cs);
            float x0 = st[r * SSTR + c], x1 = st[r * SSTR + c + 1];
            split2(x0 * cs - x1 * sn, x0 * sn + x1 * cs, Ch + off + cc, Cl + off + cc);
        }
    } else {
        // V: transpose + hi/lo split into vt[d, t]
        #pragma unroll
        for (int i = 0; i < 2; i++)
            #pragma unroll
            for (int j = 0; j < 4; j++)
                wmma::store_matrix_sync(st + (wn * 64 + j * 16) * SSTR + wm * 32 + i * 16,
                                        acc[i][j], SSTR, wmma::mem_col_major);
        __syncthreads();
        const int d = tid >> 1;
        const int t0 = (tid & 1) * 64;
        const size_t off = (size_t)(n0 + d) * SEQ + m0 + t0;
        #pragma unroll
        for (int tt = 0; tt < 64; tt += 2)
            split2(st[d * SSTR + t0 + tt], st[d * SSTR + t0 + tt + 1],
                   g_vth + off + tt, g_vtl + off + tt);
    }
}

// ================= remaining GEMM kernels =================
// MODE 0: generic fp32 C (WO).  MODE 1: scores (triangular).  MODE 2: PV.
template<int MODE>
__global__ void __launch_bounds__(256, 2) gemm3_kernel(
    const bf16* __restrict__ Ah, const bf16* __restrict__ Al,
    const bf16* __restrict__ Bh, const bf16* __restrict__ Bl,
    float* __restrict__ Cf, bf16* __restrict__ Ch, bf16* __restrict__ Cl,
    const float* __restrict__ Linv,
    int K, int lda, int ldb, int ldc)
{
    int m0, n0;
    if (MODE == 1) {
        const int L = blockIdx.x;
        int s0i = (int)((sqrtf(8.0f * (float)L + 1.0f) - 1.0f) * 0.5f);
        while ((s0i + 1) * (s0i + 2) / 2 <= L) s0i++;
        while (s0i * (s0i + 1) / 2 > L) s0i--;
        m0 = s0i * 128;
        n0 = (L - s0i * (s0i + 1) / 2) * 128;
    } else if (MODE == 2) {
        m0 = (int)(gridDim.y - 1 - blockIdx.y) * 128;   // heavy tiles first
        n0 = blockIdx.x * 128;
    } else {
        m0 = blockIdx.y * 128;
        n0 = blockIdx.x * 128;
    }
    const int h = blockIdx.z, kvh = h >> 2;
    const int tid = threadIdx.x;
    const int warp = tid >> 5;
    const int wm = warp >> 1;
    const int wn = warp & 1;

    size_t aoff, boff, coff = 0;
    int kLen = K;
    if (MODE == 1)      { aoff = (size_t)m0 * lda + (size_t)h * HD;        boff = (size_t)n0 * ldb + (size_t)kvh * HD;
                          coff = (size_t)h * SEQ * SEQ; }
    else if (MODE == 2) { aoff = (size_t)h * SEQ * SEQ + (size_t)m0 * lda; boff = (size_t)(kvh * HD) * ldb;
                          kLen = m0 + 128; }
    else                { aoff = (size_t)m0 * lda;                         boff = (size_t)n0 * ldb; }
    const bf16* pAh = Ah + aoff; const bf16* pAl = Al + aoff;
    const bf16* pBh = Bh + boff; const bf16* pBl = Bl + boff;

    extern __shared__ __align__(16) char dsm[];
    bf16* smem = (bf16*)dsm;
    const uint32_t sm_u32 = (uint32_t)__cvta_generic_to_shared(dsm);

    GEMM3_BODY(pAh, pAl, pBh, pBl, lda, ldb, kLen)

    if (MODE == 0 || MODE == 1) {
        float* C = Cf + coff;
        #pragma unroll
        for (int i = 0; i < 2; i++)
            #pragma unroll
            for (int j = 0; j < 4; j++)
                wmma::store_matrix_sync(C + (size_t)(m0 + wm * 32 + i * 16) * ldc + n0 + wn * 64 + j * 16,
                                        acc[i][j], ldc, wmma::mem_row_major);
    } else {
        float* st = (float*)dsm;
        #pragma unroll
        for (int i = 0; i < 2; i++)
            #pragma unroll
            for (int j = 0; j < 4; j++)
                wmma::store_matrix_sync(st + (wm * 32 + i * 16) * SSTR + wn * 64 + j * 16,
                                        acc[i][j], SSTR, wmma::mem_row_major);
        __syncthreads();
        const int r = tid >> 1;
        const int c0 = (tid & 1) * 64;
        const float sc = Linv[h * SEQ + m0 + r];   // softmax normalization
        const size_t off = (size_t)(m0 + r) * ldc + (size_t)h * HD + c0;
        #pragma unroll
        for (int cc = 0; cc < 64; cc += 2)
            split2(st[r * SSTR + c0 + cc] * sc, st[r * SSTR + c0 + cc + 1] * sc,
                   Ch + off + cc, Cl + off + cc);
    }
}

// ================= small kernels =================
__global__ void split_kernel(const float4* __restrict__ s, uint4* __restrict__ h4,
                             uint4* __restrict__ l4, int n8) {
    const int i0 = blockIdx.x * 1024 + threadIdx.x;
    #pragma unroll
    for (int u = 0; u < 4; u++) {
        const int i = i0 + u * 256;
        if (i >= n8) return;
        float4 v0 = s[2 * i], v1 = s[2 * i + 1];
        float f[8] = { v0.x, v0.y, v0.z, v0.w, v1.x, v1.y, v1.z, v1.w };
        bf16 hb[8], lb[8];
        #pragma unroll
        for (int j = 0; j < 8; j++) {
            hb[j] = __float2bfloat16(f[j]);
            lb[j] = __float2bfloat16(f[j] - __bfloat162float(hb[j]));
        }
        h4[i] = *(uint4*)hb;
        l4[i] = *(uint4*)lb;
    }
}

// warp-per-row softmax, exp-once, unnormalized e-values + 1/sum.
__global__ void softmax_kernel(const float* __restrict__ scores, bf16* __restrict__ ph,
                               bf16* __restrict__ pl, float* __restrict__ linv) {
    extern __shared__ float cache[];   // 8 warps x 2048 floats = 64KB
    const int warp = threadIdx.x >> 5, lane = threadIdx.x & 31;
    const int s = blockIdx.x * 8 + warp;
    const int h = blockIdx.y;
    const float* row = scores + ((size_t)h * SEQ + s) * SEQ;
    bf16* prh = ph + ((size_t)h * SEQ + s) * SEQ;
    bf16* prl = pl + ((size_t)h * SEQ + s) * SEQ;
    float* cr = cache + warp * SEQ;
    const int len = s + 1;
    const int zlen = ((s >> 7) + 1) << 7;

    float mx = -3.402823466e38f;
    for (int t = lane; t < len; t += 32) {
        float v = row[t] * SOFT_SCALE;
        cr[t] = v;
        mx = fmaxf(mx, v);
    }
    #pragma unroll
    for (int o = 16; o > 0; o >>= 1) mx = fmaxf(mx, __shfl_xor_sync(0xffffffffu, mx, o));

    float sum = 0.f;
    for (int t = lane; t < len; t += 32) {
        float e = __expf(cr[t] - mx);
        sum += e;
        bf16 hh = __float2bfloat16(e);
        prh[t] = hh;
        prl[t] = __float2bfloat16(e - __bfloat162float(hh));
    }
    #pragma unroll
    for (int o = 16; o > 0; o >>= 1) sum += __shfl_xor_sync(0xffffffffu, sum, o);
    if (lane == 0) linv[h * SEQ + s] = 1.0f / sum;

    const bf16 z = __float2bfloat16(0.f);
    for (int t = len + lane; t < zlen; t += 32) { prh[t] = z; prl[t] = z; }
}

// ================= host =================
extern "C" void kernel_launch(void* const* d_in, const int* in_sizes, int n_in,
                              void* d_out, int out_size) {
    (void)in_sizes; (void)n_in; (void)out_size;
    const float* x  = (const float*)d_in[0];
    const float* wq = (const float*)d_in[1];
    const float* wk = (const float*)d_in[2];
    const float* wv = (const float*)d_in[3];
    const float* wo = (const float*)d_in[4];
    float* out = (float*)d_out;

    float *scores, *linv;
    bf16 *xh, *xl, *wqh, *wql, *wkh, *wkl, *wvh, *wvl, *woh, *wol;
    bf16 *qh, *ql, *kh, *kl, *vth, *vtl, *ph, *pl, *ah, *al;
    cudaGetSymbolAddress((void**)&scores, g_scores);
    cudaGetSymbolAddress((void**)&linv, g_linv);
    cudaGetSymbolAddress((void**)&xh, g_xh);  cudaGetSymbolAddress((void**)&xl, g_xl);
    cudaGetSymbolAddress((void**)&wqh, g_wqh); cudaGetSymbolAddress((void**)&wql, g_wql);
    cudaGetSymbolAddress((void**)&wkh, g_wkh); cudaGetSymbolAddress((void**)&wkl, g_wkl);
    cudaGetSymbolAddress((void**)&wvh, g_wvh); cudaGetSymbolAddress((void**)&wvl, g_wvl);
    cudaGetSymbolAddress((void**)&woh, g_woh); cudaGetSymbolAddress((void**)&wol, g_wol);
    cudaGetSymbolAddress((void**)&qh, g_qh);  cudaGetSymbolAddress((void**)&ql, g_ql);
    cudaGetSymbolAddress((void**)&kh, g_kh);  cudaGetSymbolAddress((void**)&kl, g_kl);
    cudaGetSymbolAddress((void**)&vth, g_vth); cudaGetSymbolAddress((void**)&vtl, g_vtl);
    cudaGetSymbolAddress((void**)&ph, g_ph);  cudaGetSymbolAddress((void**)&pl, g_pl);
    cudaGetSymbolAddress((void**)&ah, g_ah);  cudaGetSymbolAddress((void**)&al, g_al);

    cudaFuncSetAttribute(qkv_kernel, cudaFuncAttributeMaxDynamicSharedMemorySize, GSMEM);
    cudaFuncSetAttribute(gemm3_kernel<0>, cudaFuncAttributeMaxDynamicSharedMemorySize, GSMEM);
    cudaFuncSetAttribute(gemm3_kernel<1>, cudaFuncAttributeMaxDynamicSharedMemorySize, GSMEM);
    cudaFuncSetAttribute(gemm3_kernel<2>, cudaFuncAttributeMaxDynamicSharedMemorySize, GSMEM);
    cudaFuncSetAttribute(softmax_kernel, cudaFuncAttributeMaxDynamicSharedMemorySize, 8 * SEQ * 4);

    // split inputs to bf16 hi/lo  (n8 = floats/8)
    split_kernel<<<SEQ*DIM/8/1024, 256>>>((const float4*)x,  (uint4*)xh,  (uint4*)xl,  SEQ*DIM/8);
    split_kernel<<<DIM*DIM/8/1024, 256>>>((const float4*)wq, (uint4*)wqh, (uint4*)wql, DIM*DIM/8);
    split_kernel<<<KVD*DIM/8/1024, 256>>>((const float4*)wk, (uint4*)wkh, (uint4*)wkl, KVD*DIM/8);
    split_kernel<<<KVD*DIM/8/1024, 256>>>((const float4*)wv, (uint4*)wvh, (uint4*)wvl, KVD*DIM/8);
    split_kernel<<<DIM*DIM/8/1024, 256>>>((const float4*)wo, (uint4*)woh, (uint4*)wol, DIM*DIM/8);

    // fused Q/K/V projections (RoPE for Q/K, transpose for V), one packed launch
    qkv_kernel<<<768, 256, GSMEM>>>();

    // attention
    gemm3_kernel<1><<<dim3(136, 1, NH), 256, GSMEM>>>(qh, ql, kh, kl, scores, nullptr, nullptr, nullptr, HD, DIM, KVD, SEQ);
    softmax_kernel<<<dim3(SEQ/8, NH), 256, 8*SEQ*4>>>(scores, ph, pl, linv);
    gemm3_kernel<2><<<dim3(1, SEQ/128, NH), 256, GSMEM>>>(ph, pl, vth, vtl, nullptr, ah, al, linv, 0, SEQ, SEQ, DIM);

    // output projection
    gemm3_kernel<0><<<dim3(DIM/128, SEQ/128), 256, GSMEM>>>(ah, al, woh, wol, out, nullptr, nullptr, nullptr, DIM, DIM, DIM, DIM);
}